// round 7
// baseline (speedup 1.0000x reference)
#include <cuda_runtime.h>
#include <math.h>
#include <float.h>

// LSH attention: B=16, S=4096, D=64, H=8 hashes, bucket_size=64
#define BB 16
#define SS 4096
#define DD 64
#define HH 8
#define NBK 64          // n_buckets
#define CPB 512         // chunks per batch = H * n_buckets
#define TILES_PER_B 64  // S / 64

typedef unsigned long long u64;

// ---------------- scratch (device globals; no allocation allowed) ----------------
__device__ unsigned char g_bucket[BB * HH * SS];          // 512 KB
__device__ int           g_st[BB * HH * SS];              // 2 MB  sorted original positions
__device__ float         g_norm[BB * SS];                 // 256 KB
__device__ float         g_logits[BB * HH * SS];          // 2 MB
__device__ float         g_o[(size_t)BB * HH * SS * DD];  // 134 MB

// packed f32x2 FMA (SASS FFMA2). Each 32-bit half is an independent FMA.
__device__ __forceinline__ void ffma2(u64 &acc, u64 a, u64 b) {
    asm volatile("fma.rn.f32x2 %0, %1, %2, %0;" : "+l"(acc) : "l"(a), "l"(b));
}
__device__ __forceinline__ u64 pack2(float a, float b) {
    u64 r;
    asm("mov.b64 %0, {%1, %2};" : "=l"(r) : "f"(a), "f"(b));
    return r;
}
__device__ __forceinline__ float lo2(u64 x) { return __uint_as_float((unsigned)(x & 0xffffffffu)); }
__device__ __forceinline__ float hi2(u64 x) { return __uint_as_float((unsigned)(x >> 32)); }
__device__ __forceinline__ float fsum2(u64 x) { return lo2(x) + hi2(x); }

// =====================================================================
// Probe kernel: shifts ncu's skip-5 capture slot onto k_attn.
// =====================================================================
__global__ void k_probe() {}

// =====================================================================
// Kernel 1: hash projection + argmax buckets + token norms
// (unchanged from R6 — bit-stable vs reference at rel_err 4.4e-4)
// =====================================================================
__global__ void __launch_bounds__(512) k_hash(const float* __restrict__ qk,
                                              const float* __restrict__ rot) {
    extern __shared__ float sm1[];
    float* qs   = sm1;               // [64][65]
    float* rotF = sm1 + 64 * 65;     // [64][260] f-major

    int tid = threadIdx.x;
    int b   = blockIdx.x >> 6;
    int tb  = (blockIdx.x & 63) * 64;

    for (int i = tid; i < 64 * 64; i += 512) {
        int r = i >> 6, f = i & 63;
        qs[r * 65 + f] = qk[((size_t)(b * SS + tb + r)) * DD + f];
    }
    for (int i = tid; i < 64 * 256; i += 512) {
        int f = i >> 8, c = i & 255;
        rotF[f * 260 + c] = rot[i];
    }
    __syncthreads();

    if (tid < 64) {
        float ssq = 0.f;
        #pragma unroll 8
        for (int f = 0; f < 64; f++) { float x = qs[tid * 65 + f]; ssq += x * x; }
        g_norm[b * SS + tb + tid] = sqrtf(ssq);
    }

    {
        int h   = tid >> 6;          // uniform within each warp
        int tok = tid & 63;

        u64 acc[16];
        #pragma unroll
        for (int i = 0; i < 16; i++) acc[i] = 0ull;

        for (int f = 0; f < 64; f++) {
            float qf = qs[tok * 65 + f];
            u64 qq = pack2(qf, qf);
            const float4* rp = (const float4*)&rotF[f * 260 + h * 32];
            #pragma unroll
            for (int i4 = 0; i4 < 8; i4++) {
                float4 r4 = rp[i4];
                ffma2(acc[2 * i4],     qq, pack2(r4.x, r4.y));
                ffma2(acc[2 * i4 + 1], qq, pack2(r4.z, r4.w));
            }
        }

        float best = lo2(acc[0]); int bi = 0;
        #pragma unroll
        for (int i = 0; i < 16; i++) {
            float vl = lo2(acc[i]), vh = hi2(acc[i]);
            int cl = 2 * i, ch = 2 * i + 1;
            if (cl > 0 && vl > best) { best = vl; bi = cl; }
            if (vh > best)           { best = vh; bi = ch; }
        }
        #pragma unroll
        for (int i = 0; i < 16; i++) {
            float vl = -lo2(acc[i]), vh = -hi2(acc[i]);
            if (vl > best) { best = vl; bi = 32 + 2 * i; }
            if (vh > best) { best = vh; bi = 32 + 2 * i + 1; }
        }
        g_bucket[(size_t)(b * HH + h) * SS + tb + tok] = (unsigned char)bi;
    }
}

// =====================================================================
// Kernel 2: stable counting sort per (b,h) by (bucket, position)
// =====================================================================
__global__ void __launch_bounds__(256) k_sort() {
    __shared__ unsigned char bk[SS];
    __shared__ int cnt[64];
    __shared__ int off[64];
    int tid = threadIdx.x;
    int b = blockIdx.x >> 3, h = blockIdx.x & 7;
    size_t base = (size_t)(b * HH + h) * SS;

    if (tid < 64) cnt[tid] = 0;
    __syncthreads();
    for (int t = tid; t < SS; t += 256) {
        unsigned char bb = g_bucket[base + t];
        bk[t] = bb;
        atomicAdd(&cnt[bb], 1);
    }
    __syncthreads();
    if (tid == 0) {
        int run = 0;
        for (int j = 0; j < 64; j++) { off[j] = run; run += cnt[j]; }
    }
    __syncthreads();
    if (tid < 64) {
        int p = off[tid];
        unsigned char me = (unsigned char)tid;
        for (int t = 0; t < SS; t++) {
            if (bk[t] == me) g_st[base + p++] = t;
        }
    }
}

// =====================================================================
// Kernel 3: chunked attention. One block per (b, chunk). 256 threads,
// 3 CTAs/SM (smem overlay + register softmax).
// SMEM (dynamic, 66560 B):
//   [attn 64x132 floats = 33792 B]  <- overlays ks8 (dead after GEMM1)
//   [vTf  64x128 floats = 32768 B]
//   ks8 = (u64*)base: 128 rows x 32 u64, XOR swizzle (GEMM1 operand)
// =====================================================================
__global__ void __launch_bounds__(256, 3) k_attn(const float* __restrict__ qk,
                                                 const float* __restrict__ v) {
    extern __shared__ float sm3[];
    float* attn = sm3;                       // [64][132] (phase 2)
    u64*   ks8  = (u64*)sm3;                 // 128*32 u64 (phase 1)
    float* vTf  = sm3 + 8448;                // 64*128 floats

    __shared__ int   tkv[128];
    __shared__ float sQ[64];

    int tid = threadIdx.x;
    int b = blockIdx.x >> 9;
    int c = blockIdx.x & 511;
    int cp = (c + CPB - 1) & (CPB - 1);
    int h = c >> 6, hp = cp >> 6;
    size_t baseq = (size_t)(b * HH + h)  * SS + (c  & 63) * 64;
    size_t basep = (size_t)(b * HH + hp) * SS + (cp & 63) * 64;

    if (tid < 64) {
        int t = g_st[baseq + tid];
        tkv[tid] = t;
        sQ[tid] = fmaxf(g_norm[b * SS + t], 1e-12f);
    } else if (tid < 128) {
        tkv[tid] = g_st[basep + tid - 64];
    }
    __syncthreads();

    // gather K (normalized, u64-swizzled) and V (transposed, 16B-swizzled)
    for (int i = tid; i < 128 * 16; i += 256) {
        int j = i >> 4, q4 = i & 15;
        int t = tkv[j];
        size_t rowoff = ((size_t)b * SS + t) * DD + q4 * 4;
        float4 kq = *(const float4*)(qk + rowoff);
        float rn = 1.0f / fmaxf(g_norm[b * SS + t], 1e-12f);
        int rb = j << 5, rm = j & 31;
        ks8[rb + ((2 * q4)     ^ rm)] = pack2(kq.x * rn, kq.y * rn);
        ks8[rb + ((2 * q4 + 1) ^ rm)] = pack2(kq.z * rn, kq.w * rn);

        float4 vv = *(const float4*)(v + rowoff);
        int d0 = q4 * 4, jw = j >> 2, jl = j & 3;
        vTf[((d0 + 0) * 32 + (jw ^ ((d0 + 0) & 31))) * 4 + jl] = vv.x;
        vTf[((d0 + 1) * 32 + (jw ^ ((d0 + 1) & 31))) * 4 + jl] = vv.y;
        vTf[((d0 + 2) * 32 + (jw ^ ((d0 + 2) & 31))) * 4 + jl] = vv.z;
        vTf[((d0 + 3) * 32 + (jw ^ ((d0 + 3) & 31))) * 4 + jl] = vv.w;
    }
    __syncthreads();

    int ty = tid >> 5, tx = tid & 31;

    // GEMM1 (reads ks8): G[i][j] = k_i . k_j, 8x4 f32x2 tile per thread
    u64 acc[8][4];
    #pragma unroll
    for (int rr = 0; rr < 8; rr++)
        #pragma unroll
        for (int jj = 0; jj < 4; jj++) acc[rr][jj] = 0ull;

    for (int w = 0; w < 32; w++) {      // f = 2w
        u64 kv2[4];
        #pragma unroll
        for (int jj = 0; jj < 4; jj++) {
            int r = tx + 32 * jj;                    // r & 31 == tx
            kv2[jj] = ks8[(r << 5) + (w ^ tx)];      // conflict-free column
        }
        #pragma unroll
        for (int rr = 0; rr < 8; rr++) {
            int r = ty * 8 + rr;
            u64 qv = ks8[(r << 5) + (w ^ (r & 31))]; // warp-uniform broadcast
            #pragma unroll
            for (int jj = 0; jj < 4; jj++)
                ffma2(acc[rr][jj], qv, kv2[jj]);
        }
    }

    // masks + softmax ENTIRELY in registers (row fully owned by one warp)
    float a[8][4];
    int tkcol[4];
    #pragma unroll
    for (int jj = 0; jj < 4; jj++) tkcol[jj] = tkv[tx + 32 * jj];

    #pragma unroll
    for (int rr = 0; rr < 8; rr++) {
        int row = ty * 8 + rr;
        int tq  = tkv[row];
        float s = sQ[row] * 0.125f;   // norm_i * D^-0.5
        #pragma unroll
        for (int jj = 0; jj < 4; jj++) {
            float val = fsum2(acc[rr][jj]) * s;
            int tk = tkcol[jj];
            if (tq < tk)  val = -3.402823466e38f;   // causal mask
            if (tq == tk) val = -50000.0f;          // self mask
            a[rr][jj] = val;
        }
        float m = fmaxf(fmaxf(a[rr][0], a[rr][1]), fmaxf(a[rr][2], a[rr][3]));
        #pragma unroll
        for (int o = 16; o > 0; o >>= 1) m = fmaxf(m, __shfl_xor_sync(0xffffffffu, m, o));
        float sum = 0.f;
        #pragma unroll
        for (int jj = 0; jj < 4; jj++) { a[rr][jj] = __expf(a[rr][jj] - m); sum += a[rr][jj]; }
        #pragma unroll
        for (int o = 16; o > 0; o >>= 1) sum += __shfl_xor_sync(0xffffffffu, sum, o);
        float inv = 1.0f / sum;
        #pragma unroll
        for (int jj = 0; jj < 4; jj++) a[rr][jj] *= inv;
        if (tx == 0)
            g_logits[(size_t)(b * HH + h) * SS + tq] = m + __logf(sum);
    }
    __syncthreads();   // all warps done reading ks8 before overlay write

    #pragma unroll
    for (int rr = 0; rr < 8; rr++) {
        int row = ty * 8 + rr;
        #pragma unroll
        for (int jj = 0; jj < 4; jj++)
            attn[row * 132 + tx + 32 * jj] = a[rr][jj];
    }
    __syncthreads();

    // GEMM2: out[i][d] = sum_j attn[i][j] * vT[d][j]; 8x2 tile, j-step 4
    {
        u64 acc2[8][2];
        #pragma unroll
        for (int rr = 0; rr < 8; rr++) { acc2[rr][0] = 0ull; acc2[rr][1] = 0ull; }

        for (int js = 0; js < 128; js += 4) {
            int jw = js >> 2;
            float4 w04 = *(const float4*)&vTf[(tx * 32 + (jw ^ tx)) * 4];         // d = tx
            float4 w14 = *(const float4*)&vTf[((tx + 32) * 32 + (jw ^ tx)) * 4];  // d = tx+32
            u64 w0lo = pack2(w04.x, w04.y), w0hi = pack2(w04.z, w04.w);
            u64 w1lo = pack2(w14.x, w14.y), w1hi = pack2(w14.z, w14.w);
            #pragma unroll
            for (int rr = 0; rr < 8; rr++) {
                const float4 a4 = *(const float4*)&attn[(ty * 8 + rr) * 132 + js]; // uniform
                u64 alo = pack2(a4.x, a4.y), ahi = pack2(a4.z, a4.w);
                ffma2(acc2[rr][0], alo, w0lo);
                ffma2(acc2[rr][0], ahi, w0hi);
                ffma2(acc2[rr][1], alo, w1lo);
                ffma2(acc2[rr][1], ahi, w1hi);
            }
        }
        #pragma unroll
        for (int rr = 0; rr < 8; rr++) {
            int row = ty * 8 + rr;
            int t = tkv[row];
            float* dst = &g_o[((size_t)(b * HH + h) * SS + t) * DD];
            dst[tx]      = fsum2(acc2[rr][0]);
            dst[tx + 32] = fsum2(acc2[rr][1]);
        }
    }
}

// =====================================================================
// Kernel 4: combine hash rounds via softmax over per-hash logits
// =====================================================================
__global__ void __launch_bounds__(256) k_combine(float* __restrict__ out) {
    int gid = blockIdx.x * 256 + threadIdx.x;   // B*S*4 total
    int token = gid >> 2, q = gid & 3;
    int b = token >> 12, t = token & 4095;

    float l[HH];
    #pragma unroll
    for (int h = 0; h < HH; h++)
        l[h] = g_logits[(size_t)(b * HH + h) * SS + t];
    float m = l[0];
    #pragma unroll
    for (int h = 1; h < HH; h++) m = fmaxf(m, l[h]);
    float w[HH]; float sum = 0.f;
    #pragma unroll
    for (int h = 0; h < HH; h++) { w[h] = expf(l[h] - m); sum += w[h]; }
    float inv = 1.0f / sum;

    float4 acc[4];
    #pragma unroll
    for (int k = 0; k < 4; k++) acc[k] = make_float4(0.f, 0.f, 0.f, 0.f);
    #pragma unroll
    for (int h = 0; h < HH; h++) {
        const float4* src =
            (const float4*)&g_o[((size_t)(b * HH + h) * SS + t) * DD + q * 16];
        float wh = w[h] * inv;
        #pragma unroll
        for (int k = 0; k < 4; k++) {
            float4 x = src[k];
            acc[k].x += x.x * wh; acc[k].y += x.y * wh;
            acc[k].z += x.z * wh; acc[k].w += x.w * wh;
        }
    }
    float4* dst = (float4*)(out + ((size_t)b * SS + t) * DD + q * 16);
    #pragma unroll
    for (int k = 0; k < 4; k++) dst[k] = acc[k];
}

// =====================================================================
extern "C" void kernel_launch(void* const* d_in, const int* in_sizes, int n_in,
                              void* d_out, int out_size) {
    const float* qk  = (const float*)d_in[0];
    const float* v   = (const float*)d_in[1];
    const float* rot = (const float*)d_in[2];
    float* out = (float*)d_out;

    const int smem1 = (64 * 65 + 64 * 260) * 4;   // 83200 B
    const int smem3 = (8448 + 8192) * 4;          // 66560 B -> 3 CTAs/SM
    cudaFuncSetAttribute(k_hash, cudaFuncAttributeMaxDynamicSharedMemorySize, smem1);
    cudaFuncSetAttribute(k_attn, cudaFuncAttributeMaxDynamicSharedMemorySize, smem3);

    k_hash<<<BB * TILES_PER_B, 512, smem1>>>(qk, rot);
    k_sort<<<BB * HH, 256>>>();
    k_probe<<<1, 32>>>();   // shifts ncu skip-5 capture onto k_attn
    k_attn<<<BB * CPB, 256, smem3>>>(qk, v);
    k_combine<<<BB * SS * 4 / 256, 256>>>(out);
}

// round 8
// speedup vs baseline: 1.2327x; 1.2327x over previous
#include <cuda_runtime.h>
#include <math.h>
#include <float.h>

// LSH attention: B=16, S=4096, D=64, H=8 hashes, bucket_size=64
#define BB 16
#define SS 4096
#define DD 64
#define HH 8
#define NBK 64          // n_buckets
#define CPB 512         // chunks per batch = H * n_buckets
#define TILES_PER_B 64  // S / 64

typedef unsigned long long u64;

// ---------------- scratch (device globals; no allocation allowed) ----------------
__device__ unsigned char g_bucket[BB * HH * SS];          // 512 KB
__device__ int           g_st[BB * HH * SS];              // 2 MB  sorted original positions
__device__ float         g_norm[BB * SS];                 // 256 KB
__device__ float         g_logits[BB * HH * SS];          // 2 MB
__device__ float         g_o[(size_t)BB * HH * SS * DD];  // 134 MB

// packed f32x2 FMA (SASS FFMA2). Each 32-bit half is an independent FMA.
__device__ __forceinline__ void ffma2(u64 &acc, u64 a, u64 b) {
    asm volatile("fma.rn.f32x2 %0, %1, %2, %0;" : "+l"(acc) : "l"(a), "l"(b));
}
__device__ __forceinline__ u64 pack2(float a, float b) {
    u64 r;
    asm("mov.b64 %0, {%1, %2};" : "=l"(r) : "f"(a), "f"(b));
    return r;
}
__device__ __forceinline__ float lo2(u64 x) { return __uint_as_float((unsigned)(x & 0xffffffffu)); }
__device__ __forceinline__ float hi2(u64 x) { return __uint_as_float((unsigned)(x >> 32)); }
__device__ __forceinline__ float fsum2(u64 x) { return lo2(x) + hi2(x); }

// =====================================================================
// Probe kernel: keeps ncu's skip-5 capture slot on k_attn.
// =====================================================================
__global__ void k_probe() {}

// =====================================================================
// Kernel 1: hash projection + argmax buckets + token norms
// (unchanged — bit-stable vs reference at rel_err 4.4e-4)
// =====================================================================
__global__ void __launch_bounds__(512) k_hash(const float* __restrict__ qk,
                                              const float* __restrict__ rot) {
    extern __shared__ float sm1[];
    float* qs   = sm1;               // [64][65]
    float* rotF = sm1 + 64 * 65;     // [64][260] f-major

    int tid = threadIdx.x;
    int b   = blockIdx.x >> 6;
    int tb  = (blockIdx.x & 63) * 64;

    for (int i = tid; i < 64 * 64; i += 512) {
        int r = i >> 6, f = i & 63;
        qs[r * 65 + f] = qk[((size_t)(b * SS + tb + r)) * DD + f];
    }
    for (int i = tid; i < 64 * 256; i += 512) {
        int f = i >> 8, c = i & 255;
        rotF[f * 260 + c] = rot[i];
    }
    __syncthreads();

    if (tid < 64) {
        float ssq = 0.f;
        #pragma unroll 8
        for (int f = 0; f < 64; f++) { float x = qs[tid * 65 + f]; ssq += x * x; }
        g_norm[b * SS + tb + tid] = sqrtf(ssq);
    }

    {
        int h   = tid >> 6;          // uniform within each warp
        int tok = tid & 63;

        u64 acc[16];
        #pragma unroll
        for (int i = 0; i < 16; i++) acc[i] = 0ull;

        for (int f = 0; f < 64; f++) {
            float qf = qs[tok * 65 + f];
            u64 qq = pack2(qf, qf);
            const float4* rp = (const float4*)&rotF[f * 260 + h * 32];
            #pragma unroll
            for (int i4 = 0; i4 < 8; i4++) {
                float4 r4 = rp[i4];
                ffma2(acc[2 * i4],     qq, pack2(r4.x, r4.y));
                ffma2(acc[2 * i4 + 1], qq, pack2(r4.z, r4.w));
            }
        }

        float best = lo2(acc[0]); int bi = 0;
        #pragma unroll
        for (int i = 0; i < 16; i++) {
            float vl = lo2(acc[i]), vh = hi2(acc[i]);
            int cl = 2 * i, ch = 2 * i + 1;
            if (cl > 0 && vl > best) { best = vl; bi = cl; }
            if (vh > best)           { best = vh; bi = ch; }
        }
        #pragma unroll
        for (int i = 0; i < 16; i++) {
            float vl = -lo2(acc[i]), vh = -hi2(acc[i]);
            if (vl > best) { best = vl; bi = 32 + 2 * i; }
            if (vh > best) { best = vh; bi = 32 + 2 * i + 1; }
        }
        g_bucket[(size_t)(b * HH + h) * SS + tb + tok] = (unsigned char)bi;
    }
}

// =====================================================================
// Kernel 2: stable counting sort per (b,h) by (bucket, position)
// =====================================================================
__global__ void __launch_bounds__(256) k_sort() {
    __shared__ unsigned char bk[SS];
    __shared__ int cnt[64];
    __shared__ int off[64];
    int tid = threadIdx.x;
    int b = blockIdx.x >> 3, h = blockIdx.x & 7;
    size_t base = (size_t)(b * HH + h) * SS;

    if (tid < 64) cnt[tid] = 0;
    __syncthreads();
    for (int t = tid; t < SS; t += 256) {
        unsigned char bb = g_bucket[base + t];
        bk[t] = bb;
        atomicAdd(&cnt[bb], 1);
    }
    __syncthreads();
    if (tid == 0) {
        int run = 0;
        for (int j = 0; j < 64; j++) { off[j] = run; run += cnt[j]; }
    }
    __syncthreads();
    if (tid < 64) {
        int p = off[tid];
        unsigned char me = (unsigned char)tid;
        for (int t = 0; t < SS; t++) {
            if (bk[t] == me) g_st[base + p++] = t;
        }
    }
}

// =====================================================================
// Kernel 3: chunked attention. One block per (b, chunk). 256 threads,
// 2 CTAs/SM. ALU-minimal layouts (no XOR swizzle on hot paths):
//   ksf : u64[32 w][131 j]  f-major, linear. Column reads = lane-
//         consecutive u64 (conflict-free); row-broadcast reads uniform.
//         Addresses strength-reduce to pointer increments + immediates.
//   vTf : [64 d][128 j] floats with 16B XOR swizzle (per-lane LDS.128,
//         conflict-free; 1 XOR per 16 FFMA2 — negligible).
//   attn: [64][132] floats (write-once, broadcast-read in GEMM2).
// GEMM2 operands loaded as ulonglong2 -> FFMA2 inputs come straight
// from LDS.128 register pairs, zero pack MOVs.
// =====================================================================
__global__ void __launch_bounds__(256, 2) k_attn(const float* __restrict__ qk,
                                                 const float* __restrict__ v) {
    extern __shared__ float sm3[];
    u64*   ksf  = (u64*)sm3;                 // 32*131 u64 = 33536 B
    float* vTf  = sm3 + 8384;                // 64*128 floats = 32768 B
    float* attn = sm3 + 8384 + 8192;         // 64*132 floats = 33792 B

    __shared__ int   tkv[128];
    __shared__ float sQ[64];

    int tid = threadIdx.x;
    int b = blockIdx.x >> 9;
    int c = blockIdx.x & 511;
    int cp = (c + CPB - 1) & (CPB - 1);
    int h = c >> 6, hp = cp >> 6;
    size_t baseq = (size_t)(b * HH + h)  * SS + (c  & 63) * 64;
    size_t basep = (size_t)(b * HH + hp) * SS + (cp & 63) * 64;

    if (tid < 64) {
        int t = g_st[baseq + tid];
        tkv[tid] = t;
        sQ[tid] = fmaxf(g_norm[b * SS + t], 1e-12f);
    } else if (tid < 128) {
        tkv[tid] = g_st[basep + tid - 64];
    }
    __syncthreads();

    // gather K (normalized, f-major) and V (transposed, 16B-swizzled)
    for (int i = tid; i < 128 * 16; i += 256) {
        int j = i >> 4, q4 = i & 15;
        int t = tkv[j];
        size_t rowoff = ((size_t)b * SS + t) * DD + q4 * 4;
        float4 kq = *(const float4*)(qk + rowoff);
        float rn = 1.0f / fmaxf(g_norm[b * SS + t], 1e-12f);
        ksf[(2 * q4)     * 131 + j] = pack2(kq.x * rn, kq.y * rn);
        ksf[(2 * q4 + 1) * 131 + j] = pack2(kq.z * rn, kq.w * rn);

        float4 vv = *(const float4*)(v + rowoff);
        int d0 = q4 * 4, jw = j >> 2, jl = j & 3;
        vTf[((d0 + 0) * 32 + (jw ^ ((d0 + 0) & 31))) * 4 + jl] = vv.x;
        vTf[((d0 + 1) * 32 + (jw ^ ((d0 + 1) & 31))) * 4 + jl] = vv.y;
        vTf[((d0 + 2) * 32 + (jw ^ ((d0 + 2) & 31))) * 4 + jl] = vv.z;
        vTf[((d0 + 3) * 32 + (jw ^ ((d0 + 3) & 31))) * 4 + jl] = vv.w;
    }
    __syncthreads();

    int ty = tid >> 5, tx = tid & 31;

    // GEMM1: G[i][j] = k_i . k_j  (64 x 128), 8x4 f32x2 tile per thread
    u64 acc[8][4];
    #pragma unroll
    for (int rr = 0; rr < 8; rr++)
        #pragma unroll
        for (int jj = 0; jj < 4; jj++) acc[rr][jj] = 0ull;

    {
        const u64* pc = ksf + tx;        // column operand base (per-lane)
        const u64* pr = ksf + ty * 8;    // row operand base (warp-uniform)
        for (int w = 0; w < 32; w++) {   // f = 2w
            u64 kv2[4];
            #pragma unroll
            for (int jj = 0; jj < 4; jj++)
                kv2[jj] = pc[32 * jj];               // lane-consecutive, conflict-free
            #pragma unroll
            for (int rr = 0; rr < 8; rr++) {
                u64 qv = pr[rr];                     // uniform broadcast
                #pragma unroll
                for (int jj = 0; jj < 4; jj++)
                    ffma2(acc[rr][jj], qv, kv2[jj]);
            }
            pc += 131; pr += 131;
        }
    }

    // masks + softmax entirely in registers (row fully owned by one warp)
    float a[8][4];
    int tkcol[4];
    #pragma unroll
    for (int jj = 0; jj < 4; jj++) tkcol[jj] = tkv[tx + 32 * jj];

    #pragma unroll
    for (int rr = 0; rr < 8; rr++) {
        int row = ty * 8 + rr;
        int tq  = tkv[row];
        float s = sQ[row] * 0.125f;   // norm_i * D^-0.5
        #pragma unroll
        for (int jj = 0; jj < 4; jj++) {
            float val = fsum2(acc[rr][jj]) * s;
            int tk = tkcol[jj];
            if (tq < tk)  val = -3.402823466e38f;   // causal mask
            if (tq == tk) val = -50000.0f;          // self mask
            a[rr][jj] = val;
        }
        float m = fmaxf(fmaxf(a[rr][0], a[rr][1]), fmaxf(a[rr][2], a[rr][3]));
        #pragma unroll
        for (int o = 16; o > 0; o >>= 1) m = fmaxf(m, __shfl_xor_sync(0xffffffffu, m, o));
        float sum = 0.f;
        #pragma unroll
        for (int jj = 0; jj < 4; jj++) { a[rr][jj] = __expf(a[rr][jj] - m); sum += a[rr][jj]; }
        #pragma unroll
        for (int o = 16; o > 0; o >>= 1) sum += __shfl_xor_sync(0xffffffffu, sum, o);
        float inv = 1.0f / sum;
        #pragma unroll
        for (int jj = 0; jj < 4; jj++) a[rr][jj] *= inv;
        if (tx == 0)
            g_logits[(size_t)(b * HH + h) * SS + tq] = m + __logf(sum);
    }

    #pragma unroll
    for (int rr = 0; rr < 8; rr++) {
        int row = ty * 8 + rr;
        #pragma unroll
        for (int jj = 0; jj < 4; jj++)
            attn[row * 132 + tx + 32 * jj] = a[rr][jj];
    }
    __syncthreads();

    // GEMM2: out[i][d] = sum_j attn[i][j] * vT[d][j]; 8x2 tile, j-step 4.
    // ulonglong2 LDS.128 -> u64 operand pairs with no pack MOVs.
    {
        u64 acc2[8][2];
        #pragma unroll
        for (int rr = 0; rr < 8; rr++) { acc2[rr][0] = 0ull; acc2[rr][1] = 0ull; }

        const float* arow = attn + (ty * 8) * 132;   // warp-uniform base
        for (int jw = 0; jw < 32; jw++) {            // j = 4*jw
            ulonglong2 w0 = *(const ulonglong2*)&vTf[(tx * 32 + (jw ^ tx)) * 4];
            ulonglong2 w1 = *(const ulonglong2*)&vTf[((tx + 32) * 32 + (jw ^ tx)) * 4];
            #pragma unroll
            for (int rr = 0; rr < 8; rr++) {
                ulonglong2 av = *(const ulonglong2*)&arow[rr * 132 + 4 * jw]; // uniform
                ffma2(acc2[rr][0], av.x, w0.x);
                ffma2(acc2[rr][0], av.y, w0.y);
                ffma2(acc2[rr][1], av.x, w1.x);
                ffma2(acc2[rr][1], av.y, w1.y);
            }
        }
        #pragma unroll
        for (int rr = 0; rr < 8; rr++) {
            int row = ty * 8 + rr;
            int t = tkv[row];
            float* dst = &g_o[((size_t)(b * HH + h) * SS + t) * DD];
            dst[tx]      = fsum2(acc2[rr][0]);
            dst[tx + 32] = fsum2(acc2[rr][1]);
        }
    }
}

// =====================================================================
// Kernel 4: combine hash rounds via softmax over per-hash logits
// =====================================================================
__global__ void __launch_bounds__(256) k_combine(float* __restrict__ out) {
    int gid = blockIdx.x * 256 + threadIdx.x;   // B*S*4 total
    int token = gid >> 2, q = gid & 3;
    int b = token >> 12, t = token & 4095;

    float l[HH];
    #pragma unroll
    for (int h = 0; h < HH; h++)
        l[h] = g_logits[(size_t)(b * HH + h) * SS + t];
    float m = l[0];
    #pragma unroll
    for (int h = 1; h < HH; h++) m = fmaxf(m, l[h]);
    float w[HH]; float sum = 0.f;
    #pragma unroll
    for (int h = 0; h < HH; h++) { w[h] = expf(l[h] - m); sum += w[h]; }
    float inv = 1.0f / sum;

    float4 acc[4];
    #pragma unroll
    for (int k = 0; k < 4; k++) acc[k] = make_float4(0.f, 0.f, 0.f, 0.f);
    #pragma unroll
    for (int h = 0; h < HH; h++) {
        const float4* src =
            (const float4*)&g_o[((size_t)(b * HH + h) * SS + t) * DD + q * 16];
        float wh = w[h] * inv;
        #pragma unroll
        for (int k = 0; k < 4; k++) {
            float4 x = src[k];
            acc[k].x += x.x * wh; acc[k].y += x.y * wh;
            acc[k].z += x.z * wh; acc[k].w += x.w * wh;
        }
    }
    float4* dst = (float4*)(out + ((size_t)b * SS + t) * DD + q * 16);
    #pragma unroll
    for (int k = 0; k < 4; k++) dst[k] = acc[k];
}

// =====================================================================
extern "C" void kernel_launch(void* const* d_in, const int* in_sizes, int n_in,
                              void* d_out, int out_size) {
    const float* qk  = (const float*)d_in[0];
    const float* v   = (const float*)d_in[1];
    const float* rot = (const float*)d_in[2];
    float* out = (float*)d_out;

    const int smem1 = (64 * 65 + 64 * 260) * 4;        // 83200 B
    const int smem3 = (8384 + 8192 + 64 * 132) * 4;    // 100096 B -> 2 CTAs/SM
    cudaFuncSetAttribute(k_hash, cudaFuncAttributeMaxDynamicSharedMemorySize, smem1);
    cudaFuncSetAttribute(k_attn, cudaFuncAttributeMaxDynamicSharedMemorySize, smem3);

    k_hash<<<BB * TILES_PER_B, 512, smem1>>>(qk, rot);
    k_sort<<<BB * HH, 256>>>();
    k_probe<<<1, 32>>>();   // keeps ncu skip-5 capture on k_attn
    k_attn<<<BB * CPB, 256, smem3>>>(qk, v);
    k_combine<<<BB * SS * 4 / 256, 256>>>(out);
}